// round 3
// baseline (speedup 1.0000x reference)
#include <cuda_runtime.h>

// Problem constants
static constexpr int B_   = 8;
static constexpr int C_   = 256;
static constexpr int CQK_ = 32;
static constexpr int N_   = 4096;   // 64*64 spatial

// Scratch (static __device__ arrays: allocation-free per harness rules)
__device__ float g_q[(size_t)B_ * CQK_ * N_];   // 4 MB
__device__ float g_k[(size_t)B_ * CQK_ * N_];   // 4 MB
__device__ float g_v[(size_t)B_ * C_   * N_];   // 32 MB
__device__ float g_o[(size_t)B_ * C_   * N_];   // 32 MB

// ---------------------------------------------------------------------------
// Packed f32x2 helpers (sm_103a FFMA2 path — PTX only)
// ---------------------------------------------------------------------------
using u64_t = unsigned long long;

__device__ __forceinline__ u64_t pack2(float lo, float hi) {
    u64_t r;
    asm("mov.b64 %0, {%1, %2};" : "=l"(r) : "f"(lo), "f"(hi));
    return r;
}
__device__ __forceinline__ u64_t bcast2(float x) { return pack2(x, x); }
__device__ __forceinline__ u64_t fma2(u64_t a, u64_t b, u64_t c) {
    u64_t d;
    asm("fma.rn.f32x2 %0, %1, %2, %3;" : "=l"(d) : "l"(a), "l"(b), "l"(c));
    return d;
}
__device__ __forceinline__ u64_t mul2(u64_t a, u64_t b) {
    u64_t d;
    asm("mul.rn.f32x2 %0, %1, %2;" : "=l"(d) : "l"(a), "l"(b));
    return d;
}
__device__ __forceinline__ float2 unpack2(u64_t a) {
    float2 f;
    asm("mov.b64 {%0, %1}, %2;" : "=f"(f.x), "=f"(f.y) : "l"(a));
    return f;
}

// ---------------------------------------------------------------------------
// Projection: Y[b,m,n] = sum_c W[m,c] * X[b,c,n] + bias[m]
// W: [O, 256] row-major, X: [B, 256, N], Y: [B, O, N]
// BM in {32, 64}; block = 256 threads; BN = 64, BK = 32. Packed f32x2 inner.
// ---------------------------------------------------------------------------
template <int BM>
__global__ __launch_bounds__(256)
void proj_kernel(const float* __restrict__ W, const float* __restrict__ bias,
                 const float* __restrict__ X, float* __restrict__ Y, int O)
{
    constexpr int BK = 32;
    constexpr int BN = 64;
    constexpr int TM = BM / 16;   // 4 for BM=64, 2 for BM=32
    constexpr int TN = 4;

    __shared__ float Ws[BK][BM + 4];  // +4 pad: keeps rows 16B-aligned
    __shared__ float Xs[BK][BN];

    const int b  = blockIdx.z;
    const int m0 = blockIdx.y * BM;
    const int n0 = blockIdx.x * BN;

    const float* Xb = X + (size_t)b * C_ * N_;
    float*       Yb = Y + (size_t)b * O  * N_;

    const int tid = threadIdx.x;
    const int tm  = (tid / 16) * TM;
    const int tn  = (tid % 16) * TN;

    u64_t acc2[TM][TN / 2];
#pragma unroll
    for (int i = 0; i < TM; i++)
#pragma unroll
        for (int j = 0; j < TN / 2; j++) acc2[i][j] = pack2(0.f, 0.f);

    for (int k0 = 0; k0 < C_; k0 += BK) {
        // W tile: BM x BK, k-inner => coalesced 128B rows
        for (int i = tid; i < BM * BK; i += 256) {
            int m = i / BK, k = i % BK;
            Ws[k][m] = W[(size_t)(m0 + m) * C_ + (k0 + k)];
        }
        // X tile: BK x BN, n-inner => coalesced
        for (int i = tid; i < BK * BN / 4; i += 256) {
            int k = i / (BN / 4), n4 = (i % (BN / 4)) * 4;
            *(float4*)&Xs[k][n4] = *(const float4*)&Xb[(size_t)(k0 + k) * N_ + (n0 + n4)];
        }
        __syncthreads();

#pragma unroll
        for (int k = 0; k < BK; k++) {
            float wr[TM];
            if constexpr (TM == 4) {
                float4 w4 = *(const float4*)&Ws[k][tm];
                wr[0] = w4.x; wr[1] = w4.y; wr[2] = w4.z; wr[3] = w4.w;
            } else {
                float2 w2 = *(const float2*)&Ws[k][tm];
                wr[0] = w2.x; wr[1] = w2.y;
            }
            float4 x4 = *(const float4*)&Xs[k][tn];
            u64_t xp0 = pack2(x4.x, x4.y);
            u64_t xp1 = pack2(x4.z, x4.w);
#pragma unroll
            for (int i = 0; i < TM; i++) {
                u64_t wb = bcast2(wr[i]);
                acc2[i][0] = fma2(xp0, wb, acc2[i][0]);
                acc2[i][1] = fma2(xp1, wb, acc2[i][1]);
            }
        }
        __syncthreads();
    }

#pragma unroll
    for (int i = 0; i < TM; i++) {
        float bb = bias[m0 + tm + i];
        float2 a0 = unpack2(acc2[i][0]);
        float2 a1 = unpack2(acc2[i][1]);
        float4 o4 = make_float4(a0.x + bb, a0.y + bb, a1.x + bb, a1.y + bb);
        *(float4*)&Yb[(size_t)(m0 + tm + i) * N_ + (n0 + tn)] = o4;
    }
}

// ---------------------------------------------------------------------------
// Flash attention (fp32, packed f32x2 math):
//   Q,K: [B, 32, N]; V: [B, 256, N]; O: [B, 256, N]
//   Per CTA: one batch, 64 queries. Stream 64-key tiles with online softmax.
//   P and V tiles stored j-major with XOR swizzle for LDS.128 reads.
//   Thread: 8 channels x 8 queries in packed accumulators.
// ---------------------------------------------------------------------------
static constexpr int FL_SMEM_FLOATS =
    32 * 64      /* Qs [c][q]           */ +
    32 * 64      /* Ks [c][j]           */ +
    64 * 64      /* Ps [j][q] swizzled  */ +
    64 * 256     /* Vs [j][c] swizzled  */ +
    64 * 3       /* smax, ssum, salpha  */;
static constexpr int FL_SMEM_BYTES = FL_SMEM_FLOATS * 4;  // 99,072 B

__global__ __launch_bounds__(256, 2)
void flash_kernel(const float* __restrict__ Q, const float* __restrict__ K,
                  const float* __restrict__ V, float* __restrict__ O)
{
    extern __shared__ float sh[];
    float* Qs     = sh;                 // [32][64]
    float* Ks     = Qs + 32 * 64;       // [32][64]
    float* Ps     = Ks + 32 * 64;       // [64][64]  j-major, swizzled
    float* Vs     = Ps + 64 * 64;       // [64][256] j-major, swizzled
    float* smax   = Vs + 64 * 256;      // [64]
    float* ssum   = smax + 64;          // [64]
    float* salpha = ssum + 64;          // [64]

    const int tid = threadIdx.x;
    const int b   = blockIdx.y;
    const int q0  = blockIdx.x * 64;

    const float* Qb = Q + (size_t)b * CQK_ * N_;
    const float* Kb = K + (size_t)b * CQK_ * N_;
    const float* Vb = V + (size_t)b * C_   * N_;

    // PV mapping: 8 queries (contiguous) x 8 channels (contiguous)
    const int q0t = (tid & 7)  * 8;
    const int c0t = (tid >> 3) * 8;
    // S mapping: 4 queries x 4 keys micro-tile of the 64x64 score tile.
    // Row group = 16 lanes sharing si0 (same half-warp) -> shfl reductions.
    const int si0 = (tid >> 4) * 4;
    const int sj0 = (tid & 15) * 4;

    // Load Q tile [32][64]
    for (int i = tid; i < 512; i += 256) {
        int c = i >> 4, j4 = (i & 15) * 4;
        *(float4*)&Qs[c * 64 + j4] = *(const float4*)&Qb[(size_t)c * N_ + q0 + j4];
    }
    if (tid < 64) { smax[tid] = -1e30f; ssum[tid] = 0.f; }

    u64_t acc2[8][4];  // [qq][cc pair]
#pragma unroll
    for (int i = 0; i < 8; i++)
#pragma unroll
        for (int j = 0; j < 4; j++) acc2[i][j] = pack2(0.f, 0.f);

    for (int kt = 0; kt < N_ / 64; kt++) {
        const int j0 = kt * 64;

        // K tile [32][64] straight
        for (int i = tid; i < 512; i += 256) {
            int c = i >> 4, j4 = (i & 15) * 4;
            *(float4*)&Ks[c * 64 + j4] = *(const float4*)&Kb[(size_t)c * N_ + j0 + j4];
        }
        // V tile transposed to [j][c] with XOR swizzle (c ^ ((j>>3)&7)<<2)
        for (int i = tid; i < 4096; i += 256) {
            int c = i >> 4, j4 = (i & 15) * 4;
            float4 v4 = *(const float4*)&Vb[(size_t)c * N_ + j0 + j4];
            int xs = ((j4 >> 3) & 7) << 2;   // constant over the 4 j's (same 8-block)
            int cs = c ^ xs;
            Vs[(j4 + 0) * 256 + cs] = v4.x;
            Vs[(j4 + 1) * 256 + cs] = v4.y;
            Vs[(j4 + 2) * 256 + cs] = v4.z;
            Vs[(j4 + 3) * 256 + cs] = v4.w;
        }
        __syncthreads();

        // --- S = Q^T K (packed) ---
        u64_t s2[4][2];
#pragma unroll
        for (int i = 0; i < 4; i++) { s2[i][0] = pack2(0.f, 0.f); s2[i][1] = pack2(0.f, 0.f); }
#pragma unroll 8
        for (int c = 0; c < 32; c++) {
            float4 q4 = *(const float4*)&Qs[c * 64 + si0];
            float4 k4 = *(const float4*)&Ks[c * 64 + sj0];
            u64_t kp0 = pack2(k4.x, k4.y);
            u64_t kp1 = pack2(k4.z, k4.w);
            float qv[4] = {q4.x, q4.y, q4.z, q4.w};
#pragma unroll
            for (int i = 0; i < 4; i++) {
                u64_t qb = bcast2(qv[i]);
                s2[i][0] = fma2(kp0, qb, s2[i][0]);
                s2[i][1] = fma2(kp1, qb, s2[i][1]);
            }
        }
        float s[4][4];
#pragma unroll
        for (int i = 0; i < 4; i++) {
            float2 a = unpack2(s2[i][0]), bb2 = unpack2(s2[i][1]);
            s[i][0] = a.x; s[i][1] = a.y; s[i][2] = bb2.x; s[i][3] = bb2.y;
        }

        // --- online softmax: row max via shfl over the 16-lane row group ---
        float mx[4];
#pragma unroll
        for (int i = 0; i < 4; i++)
            mx[i] = fmaxf(fmaxf(s[i][0], s[i][1]), fmaxf(s[i][2], s[i][3]));
#pragma unroll
        for (int m = 1; m < 16; m <<= 1)
#pragma unroll
            for (int i = 0; i < 4; i++)
                mx[i] = fmaxf(mx[i], __shfl_xor_sync(0xffffffffu, mx[i], m));

        float mnew[4], al[4], rs[4];
#pragma unroll
        for (int i = 0; i < 4; i++) {
            float mo = smax[si0 + i];
            mnew[i] = fmaxf(mo, mx[i]);
            al[i]   = __expf(mo - mnew[i]);
            rs[i]   = 0.f;
        }

        // p = exp(s - mnew); store transposed+swizzled; accumulate row sums
        const int xs = ((sj0 >> 3) & 7) << 2;  // constant over jj (same 8-block)
        float p[4][4];
#pragma unroll
        for (int i = 0; i < 4; i++)
#pragma unroll
            for (int jj = 0; jj < 4; jj++) {
                p[i][jj] = __expf(s[i][jj] - mnew[i]);
                rs[i] += p[i][jj];
            }
#pragma unroll
        for (int jj = 0; jj < 4; jj++) {
            float4 p4 = make_float4(p[0][jj], p[1][jj], p[2][jj], p[3][jj]);
            *(float4*)&Ps[(sj0 + jj) * 64 + (si0 ^ xs)] = p4;
        }
#pragma unroll
        for (int m = 1; m < 16; m <<= 1)
#pragma unroll
            for (int i = 0; i < 4; i++)
                rs[i] += __shfl_xor_sync(0xffffffffu, rs[i], m);

        if ((tid & 15) == 0) {
#pragma unroll
            for (int i = 0; i < 4; i++) {
                smax[si0 + i]   = mnew[i];
                salpha[si0 + i] = al[i];
                ssum[si0 + i]   = ssum[si0 + i] * al[i] + rs[i];
            }
        }
        __syncthreads();

        // --- PV accumulate (packed), with alpha rescale ---
#pragma unroll
        for (int qq = 0; qq < 8; qq++) {
            u64_t ab = bcast2(salpha[q0t + qq]);
#pragma unroll
            for (int cc = 0; cc < 4; cc++)
                acc2[qq][cc] = mul2(acc2[qq][cc], ab);
        }

#pragma unroll 4
        for (int j = 0; j < 64; j++) {
            const int xj = ((j >> 3) & 7) << 2;
            float4 pa = *(const float4*)&Ps[j * 64  + (q0t ^ xj)];
            float4 pb = *(const float4*)&Ps[j * 64  + ((q0t + 4) ^ xj)];
            float4 va = *(const float4*)&Vs[j * 256 + (c0t ^ xj)];
            float4 vb = *(const float4*)&Vs[j * 256 + ((c0t + 4) ^ xj)];
            u64_t v2[4] = { pack2(va.x, va.y), pack2(va.z, va.w),
                            pack2(vb.x, vb.y), pack2(vb.z, vb.w) };
            float pv[8] = { pa.x, pa.y, pa.z, pa.w, pb.x, pb.y, pb.z, pb.w };
#pragma unroll
            for (int qq = 0; qq < 8; qq++) {
                u64_t pbb = bcast2(pv[qq]);
#pragma unroll
                for (int cc = 0; cc < 4; cc++)
                    acc2[qq][cc] = fma2(v2[cc], pbb, acc2[qq][cc]);
            }
        }
        __syncthreads();  // protect Ks/Vs/Ps/salpha for next tile
    }

    // Normalize and store
    float rl[8];
#pragma unroll
    for (int qq = 0; qq < 8; qq++) rl[qq] = 1.f / ssum[q0t + qq];

    float* Ob = O + (size_t)b * C_ * N_;
#pragma unroll
    for (int qq = 0; qq < 8; qq++) {
#pragma unroll
        for (int cc = 0; cc < 4; cc++) {
            float2 f = unpack2(acc2[qq][cc]);
            int c = c0t + cc * 2;
            Ob[(size_t)(c + 0) * N_ + q0 + q0t + qq] = f.x * rl[qq];
            Ob[(size_t)(c + 1) * N_ + q0 + q0t + qq] = f.y * rl[qq];
        }
    }
}

// ---------------------------------------------------------------------------
// kernel_launch
// Inputs (metadata order): x, Wq, bq, Wk, bk, Wv, bv, Wf, bf
// Output: float32 [B, C, H, W] = [8, 256, 64, 64]
// ---------------------------------------------------------------------------
extern "C" void kernel_launch(void* const* d_in, const int* in_sizes, int n_in,
                              void* d_out, int out_size)
{
    (void)in_sizes; (void)n_in; (void)out_size;
    const float* x  = (const float*)d_in[0];
    const float* Wq = (const float*)d_in[1];
    const float* bq = (const float*)d_in[2];
    const float* Wk = (const float*)d_in[3];
    const float* bk = (const float*)d_in[4];
    const float* Wv = (const float*)d_in[5];
    const float* bv = (const float*)d_in[6];
    const float* Wf = (const float*)d_in[7];
    const float* bf = (const float*)d_in[8];
    float* out = (float*)d_out;

    float *gq, *gk, *gv, *go;
    cudaGetSymbolAddress((void**)&gq, g_q);
    cudaGetSymbolAddress((void**)&gk, g_k);
    cudaGetSymbolAddress((void**)&gv, g_v);
    cudaGetSymbolAddress((void**)&go, g_o);

    cudaFuncSetAttribute(flash_kernel,
                         cudaFuncAttributeMaxDynamicSharedMemorySize,
                         FL_SMEM_BYTES);

    // Q, K projections: O=32
    proj_kernel<32><<<dim3(N_ / 64, 1, B_), 256>>>(Wq, bq, x, gq, CQK_);
    proj_kernel<32><<<dim3(N_ / 64, 1, B_), 256>>>(Wk, bk, x, gk, CQK_);
    // V projection: O=256
    proj_kernel<64><<<dim3(N_ / 64, C_ / 64, B_), 256>>>(Wv, bv, x, gv, C_);
    // Flash attention
    flash_kernel<<<dim3(N_ / 64, B_), 256, FL_SMEM_BYTES>>>(gq, gk, gv, go);
    // Final projection: O=256, input = attention output
    proj_kernel<64><<<dim3(N_ / 64, C_ / 64, B_), 256>>>(Wf, bf, go, out, C_);
}

// round 5
// speedup vs baseline: 1.9197x; 1.9197x over previous
#include <cuda_runtime.h>
#include <cuda_bf16.h>
#include <cstdint>

static constexpr int B_   = 8;
static constexpr int C_   = 256;
static constexpr int CQK_ = 32;
static constexpr int N_   = 4096;

// Scratch
__device__ float g_q[(size_t)B_ * CQK_ * N_];
__device__ float g_k[(size_t)B_ * CQK_ * N_];
__device__ float g_v[(size_t)B_ * C_   * N_];
__device__ float g_o[(size_t)B_ * C_   * N_];
__device__ __align__(256) __nv_bfloat16 g_qh[(size_t)B_ * N_ * CQK_];
__device__ __align__(256) __nv_bfloat16 g_ql[(size_t)B_ * N_ * CQK_];
__device__ __align__(256) __nv_bfloat16 g_kh[(size_t)B_ * N_ * CQK_];
__device__ __align__(256) __nv_bfloat16 g_kl[(size_t)B_ * N_ * CQK_];
__device__ __align__(256) __nv_bfloat16 g_vh[(size_t)B_ * C_ * N_];
__device__ __align__(256) __nv_bfloat16 g_vl[(size_t)B_ * C_ * N_];

// ---------------- packed f32x2 (projection kernels; proven on this harness) ----
using u64_t = unsigned long long;
__device__ __forceinline__ u64_t pack2(float lo, float hi) {
    u64_t r; asm("mov.b64 %0, {%1, %2};" : "=l"(r) : "f"(lo), "f"(hi)); return r;
}
__device__ __forceinline__ u64_t bcast2(float x) { return pack2(x, x); }
__device__ __forceinline__ u64_t fma2(u64_t a, u64_t b, u64_t c) {
    u64_t d; asm("fma.rn.f32x2 %0, %1, %2, %3;" : "=l"(d) : "l"(a), "l"(b), "l"(c)); return d;
}
__device__ __forceinline__ float2 unpack2(u64_t a) {
    float2 f; asm("mov.b64 {%0, %1}, %2;" : "=f"(f.x), "=f"(f.y) : "l"(a)); return f;
}

// ---------------- mma / ldmatrix / cp.async helpers (all base sm_80+ PTX) ------
__device__ __forceinline__ uint32_t smem_u32(const void* p) {
    uint32_t a;
    asm("{ .reg .u64 t; cvta.to.shared.u64 t, %1; cvt.u32.u64 %0, t; }" : "=r"(a) : "l"(p));
    return a;
}
__device__ __forceinline__ void cpa16(uint32_t dst, const void* src) {
    asm volatile("cp.async.cg.shared.global [%0], [%1], 16;" :: "r"(dst), "l"(src) : "memory");
}
#define CPA_COMMIT() asm volatile("cp.async.commit_group;" ::: "memory")
#define CPA_WAIT(n)  asm volatile("cp.async.wait_group %0;" :: "n"(n) : "memory")

__device__ __forceinline__ void ldsm4(uint32_t addr, uint32_t* r) {
    asm volatile("ldmatrix.sync.aligned.m8n8.x4.shared.b16 {%0,%1,%2,%3}, [%4];"
                 : "=r"(r[0]), "=r"(r[1]), "=r"(r[2]), "=r"(r[3]) : "r"(addr));
}
__device__ __forceinline__ void mma16816(float* d, const uint32_t* a, uint32_t b0, uint32_t b1) {
    asm volatile("mma.sync.aligned.m16n8k16.row.col.f32.bf16.bf16.f32 "
                 "{%0,%1,%2,%3}, {%4,%5,%6,%7}, {%8,%9}, {%0,%1,%2,%3};"
                 : "+f"(d[0]), "+f"(d[1]), "+f"(d[2]), "+f"(d[3])
                 : "r"(a[0]), "r"(a[1]), "r"(a[2]), "r"(a[3]), "r"(b0), "r"(b1));
}
// pack two f32 into bf16x2: element0 (lo 16 bits) = first arg
__device__ __forceinline__ uint32_t pack_bf16x2(float e0, float e1) {
    uint32_t r; asm("cvt.rn.bf16x2.f32 %0, %1, %2;" : "=r"(r) : "f"(e1), "f"(e0)); return r;
}
__device__ __forceinline__ float lo_bf16_f(uint32_t u) { return __uint_as_float(u << 16); }
__device__ __forceinline__ float hi_bf16_f(uint32_t u) { return __uint_as_float(u & 0xffff0000u); }

__device__ __forceinline__ void bf16_split(float v, __nv_bfloat16& h, __nv_bfloat16& l) {
    h = __float2bfloat16(v);
    l = __float2bfloat16(v - __bfloat162float(h));
}

// ---------------- projection (SIMT fp32, known good) ----------------
template <int BM>
__global__ __launch_bounds__(256)
void proj_kernel(const float* __restrict__ W, const float* __restrict__ bias,
                 const float* __restrict__ X, float* __restrict__ Y, int O)
{
    constexpr int BK = 32, BN = 64, TM = BM / 16;
    __shared__ float Ws[BK][BM + 4];
    __shared__ float Xs[BK][BN];

    const int b  = blockIdx.z;
    const int m0 = blockIdx.y * BM;
    const int n0 = blockIdx.x * BN;
    const float* Xb = X + (size_t)b * C_ * N_;
    float*       Yb = Y + (size_t)b * O  * N_;

    const int tid = threadIdx.x;
    const int tm  = (tid / 16) * TM;
    const int tn  = (tid % 16) * 4;

    u64_t acc2[TM][2];
#pragma unroll
    for (int i = 0; i < TM; i++) { acc2[i][0] = pack2(0.f,0.f); acc2[i][1] = pack2(0.f,0.f); }

    for (int k0 = 0; k0 < C_; k0 += BK) {
        for (int i = tid; i < BM * BK; i += 256) {
            int m = i / BK, k = i % BK;
            Ws[k][m] = W[(size_t)(m0 + m) * C_ + (k0 + k)];
        }
        for (int i = tid; i < BK * BN / 4; i += 256) {
            int k = i / (BN / 4), n4 = (i % (BN / 4)) * 4;
            *(float4*)&Xs[k][n4] = *(const float4*)&Xb[(size_t)(k0 + k) * N_ + (n0 + n4)];
        }
        __syncthreads();
#pragma unroll
        for (int k = 0; k < BK; k++) {
            float wr[TM];
            if constexpr (TM == 4) {
                float4 w4 = *(const float4*)&Ws[k][tm];
                wr[0]=w4.x; wr[1]=w4.y; wr[2]=w4.z; wr[3]=w4.w;
            } else {
                float2 w2 = *(const float2*)&Ws[k][tm];
                wr[0]=w2.x; wr[1]=w2.y;
            }
            float4 x4 = *(const float4*)&Xs[k][tn];
            u64_t xp0 = pack2(x4.x, x4.y), xp1 = pack2(x4.z, x4.w);
#pragma unroll
            for (int i = 0; i < TM; i++) {
                u64_t wb = bcast2(wr[i]);
                acc2[i][0] = fma2(xp0, wb, acc2[i][0]);
                acc2[i][1] = fma2(xp1, wb, acc2[i][1]);
            }
        }
        __syncthreads();
    }
#pragma unroll
    for (int i = 0; i < TM; i++) {
        float bb = bias[m0 + tm + i];
        float2 a0 = unpack2(acc2[i][0]), a1 = unpack2(acc2[i][1]);
        float4 o4 = make_float4(a0.x + bb, a0.y + bb, a1.x + bb, a1.y + bb);
        *(float4*)&Yb[(size_t)(m0 + tm + i) * N_ + (n0 + tn)] = o4;
    }
}

// fp32 [B,32,N] -> bf16 hi/lo [B,N,32] (transpose to row-per-token)
__global__ __launch_bounds__(256)
void convert_qk(const float* __restrict__ X, __nv_bfloat16* __restrict__ Yh,
                __nv_bfloat16* __restrict__ Yl)
{
    size_t i = (size_t)blockIdx.x * 256 + threadIdx.x;
    if (i >= (size_t)B_ * CQK_ * N_) return;
    int n = (int)(i % N_);
    size_t t = i / N_;
    int c = (int)(t % CQK_);
    int b = (int)(t / CQK_);
    float v = X[i];
    __nv_bfloat16 h, l; bf16_split(v, h, l);
    size_t o = ((size_t)b * N_ + n) * CQK_ + c;
    Yh[o] = h; Yl[o] = l;
}

// fp32 [B,C,N] -> bf16 hi/lo same layout
__global__ __launch_bounds__(256)
void convert_v(const float* __restrict__ X, __nv_bfloat16* __restrict__ Yh,
               __nv_bfloat16* __restrict__ Yl)
{
    size_t i = (size_t)blockIdx.x * 256 + threadIdx.x;
    if (i >= (size_t)B_ * C_ * N_) return;
    float v = X[i];
    __nv_bfloat16 h, l; bf16_split(v, h, l);
    Yh[i] = h; Yl[i] = l;
}

// ---------------- flash attention on mma.sync (bf16 hi/lo, fp32 accum) --------
// CTA: 256 thr / 8 warps; 64 queries; stream 64-key tiles, double-buffered.
// warps 0-3: 16 q-rows each, channels 0-127; warps 4-7: same rows, ch 128-255.
// smem rows padded: Q/K rows 80 B, V rows 144 B (conflict-free ldmatrix).
static constexpr int SQH = 0;                       // Q hi: 64*80
static constexpr int SQL = 5120;                    // Q lo
static constexpr int SKB = 10240;                   // K bufs: + bi*10240 (hi 5120 | lo 5120)
static constexpr int SVB = 30720;                   // V bufs: + bi*73728 (hi 36864 | lo 36864)
static constexpr int FL_SMEM = 30720 + 2 * 73728;   // 178176 B

__global__ __launch_bounds__(256, 1)
void flash_mma_kernel(const __nv_bfloat16* __restrict__ Qh, const __nv_bfloat16* __restrict__ Ql,
                      const __nv_bfloat16* __restrict__ Kh, const __nv_bfloat16* __restrict__ Kl,
                      const __nv_bfloat16* __restrict__ Vh, const __nv_bfloat16* __restrict__ Vl,
                      float* __restrict__ O)
{
    extern __shared__ char smem[];
    const uint32_t sb = smem_u32(smem);
    const int tid = threadIdx.x, lane = tid & 31, w = tid >> 5;
    const int qw = (w & 3) * 16;          // warp's first query row
    const int cbase = (w >> 2) * 128;     // warp's channel half
    const int b = blockIdx.y, q0 = blockIdx.x * 64;

    auto load_kv = [&](int kt, int bi) {
        const int j0 = kt * 64;
        for (int i = tid; i < 512; i += 256) {
            int half = i >> 8, r = (i >> 2) & 63, ch = i & 3;
            const __nv_bfloat16* src = (half ? Kl : Kh) + ((size_t)b * N_ + j0 + r) * CQK_ + ch * 8;
            cpa16(sb + SKB + bi * 10240 + half * 5120 + r * 80 + ch * 16, src);
        }
        for (int i = tid; i < 4096; i += 256) {
            int half = i >> 11, r = (i >> 3) & 255, ch = i & 7;
            const __nv_bfloat16* src = (half ? Vl : Vh) + ((size_t)b * C_ + r) * N_ + j0 + ch * 8;
            cpa16(sb + SVB + bi * 73728 + half * 36864 + r * 144 + ch * 16, src);
        }
    };

    // prologue: Q + tiles 0,1
    for (int i = tid; i < 512; i += 256) {
        int half = i >> 8, r = (i >> 2) & 63, ch = i & 3;
        const __nv_bfloat16* src = (half ? Ql : Qh) + ((size_t)b * N_ + q0 + r) * CQK_ + ch * 8;
        cpa16(sb + (half ? SQL : SQH) + r * 80 + ch * 16, src);
    }
    load_kv(0, 0); CPA_COMMIT();          // G0 (Q + tile0)
    load_kv(1, 1); CPA_COMMIT();          // G1 (tile1)
    CPA_WAIT(1);                          // G0 done
    __syncthreads();

    // Q A-fragments (once): [hi/lo][kchunk][4]
    uint32_t qa[2][2][4];
#pragma unroll
    for (int hl = 0; hl < 2; hl++)
#pragma unroll
        for (int kc = 0; kc < 2; kc++) {
            uint32_t addr = sb + (hl ? SQL : SQH)
                          + (uint32_t)(qw + (lane & 15)) * 80
                          + (uint32_t)(kc * 16 + (lane >> 4) * 8) * 2;
            ldsm4(addr, qa[hl][kc]);
        }

    float oacc[16][4];
#pragma unroll
    for (int i = 0; i < 16; i++)
#pragma unroll
        for (int j = 0; j < 4; j++) oacc[i][j] = 0.f;
    float rsum0 = 0.f, rsum1 = 0.f;

    for (int kt = 0; kt < 64; kt++) {
        const int bi = kt & 1;
        const uint32_t kh_b = sb + SKB + bi * 10240, kl_b = kh_b + 5120;
        const uint32_t vh_b = sb + SVB + bi * 73728, vl_b = vh_b + 36864;

        // --- S = QK^T (3-term bf16 split), accum fp32 in registers ---
        float sacc[8][4];
#pragma unroll
        for (int i = 0; i < 8; i++)
#pragma unroll
            for (int j = 0; j < 4; j++) sacc[i][j] = 0.f;

#pragma unroll
        for (int kc = 0; kc < 2; kc++)
#pragma unroll
            for (int nbp = 0; nbp < 4; nbp++) {
                uint32_t off = (uint32_t)((nbp * 2 + ((lane >> 4) & 1)) * 8 + (lane & 7)) * 80
                             + (uint32_t)(kc * 16 + ((lane >> 3) & 1) * 8) * 2;
                uint32_t bh[4], bl[4];
                ldsm4(kh_b + off, bh);
                ldsm4(kl_b + off, bl);
                mma16816(sacc[2*nbp],   qa[0][kc], bh[0], bh[1]);
                mma16816(sacc[2*nbp+1], qa[0][kc], bh[2], bh[3]);
                mma16816(sacc[2*nbp],   qa[1][kc], bh[0], bh[1]);
                mma16816(sacc[2*nbp+1], qa[1][kc], bh[2], bh[3]);
                mma16816(sacc[2*nbp],   qa[0][kc], bl[0], bl[1]);
                mma16816(sacc[2*nbp+1], qa[0][kc], bl[2], bl[3]);
            }

        // --- P = exp(S) in regs; pack to bf16 hi/lo A-fragments ---
        uint32_t pah[4][4], pal[4][4];
#pragma unroll
        for (int nb = 0; nb < 8; nb++) {
            float e0 = __expf(sacc[nb][0]);
            float e1 = __expf(sacc[nb][1]);
            float e2 = __expf(sacc[nb][2]);
            float e3 = __expf(sacc[nb][3]);
            rsum0 += e0 + e1;
            rsum1 += e2 + e3;
            int kj = nb >> 1, o = (nb & 1) * 2;
            uint32_t h01 = pack_bf16x2(e0, e1);
            uint32_t h23 = pack_bf16x2(e2, e3);
            pah[kj][o]     = h01;
            pah[kj][o + 1] = h23;
            pal[kj][o]     = pack_bf16x2(e0 - lo_bf16_f(h01), e1 - hi_bf16_f(h01));
            pal[kj][o + 1] = pack_bf16x2(e2 - lo_bf16_f(h23), e3 - hi_bf16_f(h23));
        }

        // --- O += P V^T (3-term) over this warp's 128 channels ---
#pragma unroll
        for (int cb = 0; cb < 16; cb++) {
            uint32_t rowoff = (uint32_t)(cbase + cb * 8 + (lane & 7)) * 144;
            uint32_t vfh[8], vfl[8];
#pragma unroll
            for (int kjp = 0; kjp < 2; kjp++) {
                uint32_t off = rowoff + (uint32_t)(kjp * 32 + (lane >> 3) * 8) * 2;
                ldsm4(vh_b + off, &vfh[4 * kjp]);
                ldsm4(vl_b + off, &vfl[4 * kjp]);
            }
#pragma unroll
            for (int kj = 0; kj < 4; kj++) {
                int ix = (kj >> 1) * 4 + (kj & 1) * 2;
                mma16816(oacc[cb], pah[kj], vfh[ix], vfh[ix + 1]);
                mma16816(oacc[cb], pal[kj], vfh[ix], vfh[ix + 1]);
                mma16816(oacc[cb], pah[kj], vfl[ix], vfl[ix + 1]);
            }
        }

        // --- pipeline: refill this buffer with tile kt+2 ---
        __syncthreads();                 // everyone done reading buffer bi
        if (kt + 2 < 64) load_kv(kt + 2, bi);
        CPA_COMMIT();
        CPA_WAIT(1);                     // tile kt+1 resident
        __syncthreads();
    }

    // normalize: row sums shared by lane quads (rows lane/4 and lane/4+8)
    rsum0 += __shfl_xor_sync(0xffffffffu, rsum0, 1);
    rsum0 += __shfl_xor_sync(0xffffffffu, rsum0, 2);
    rsum1 += __shfl_xor_sync(0xffffffffu, rsum1, 1);
    rsum1 += __shfl_xor_sync(0xffffffffu, rsum1, 2);
    const float inv0 = 1.f / rsum0, inv1 = 1.f / rsum1;

    const int qg = q0 + qw + (lane >> 2);
    float* Ob = g_o;  // placeholder (replaced below by param O)
    Ob = O + (size_t)b * C_ * N_;
#pragma unroll
    for (int cb = 0; cb < 16; cb++) {
        int c = cbase + cb * 8 + (lane & 3) * 2;
        Ob[(size_t)c * N_ + qg]             = oacc[cb][0] * inv0;
        Ob[(size_t)(c + 1) * N_ + qg]       = oacc[cb][1] * inv0;
        Ob[(size_t)c * N_ + qg + 8]         = oacc[cb][2] * inv1;
        Ob[(size_t)(c + 1) * N_ + qg + 8]   = oacc[cb][3] * inv1;
    }
}

// ---------------- kernel_launch ----------------
extern "C" void kernel_launch(void* const* d_in, const int* in_sizes, int n_in,
                              void* d_out, int out_size)
{
    (void)in_sizes; (void)n_in; (void)out_size;
    const float* x  = (const float*)d_in[0];
    const float* Wq = (const float*)d_in[1];
    const float* bq = (const float*)d_in[2];
    const float* Wk = (const float*)d_in[3];
    const float* bk = (const float*)d_in[4];
    const float* Wv = (const float*)d_in[5];
    const float* bv = (const float*)d_in[6];
    const float* Wf = (const float*)d_in[7];
    const float* bf = (const float*)d_in[8];
    float* out = (float*)d_out;

    float *gq, *gk, *gv, *go;
    __nv_bfloat16 *qh, *ql, *kh, *kl, *vh, *vl;
    cudaGetSymbolAddress((void**)&gq, g_q);
    cudaGetSymbolAddress((void**)&gk, g_k);
    cudaGetSymbolAddress((void**)&gv, g_v);
    cudaGetSymbolAddress((void**)&go, g_o);
    cudaGetSymbolAddress((void**)&qh, g_qh);
    cudaGetSymbolAddress((void**)&ql, g_ql);
    cudaGetSymbolAddress((void**)&kh, g_kh);
    cudaGetSymbolAddress((void**)&kl, g_kl);
    cudaGetSymbolAddress((void**)&vh, g_vh);
    cudaGetSymbolAddress((void**)&vl, g_vl);

    cudaFuncSetAttribute(flash_mma_kernel,
                         cudaFuncAttributeMaxDynamicSharedMemorySize, FL_SMEM);

    // projections (fp32)
    proj_kernel<32><<<dim3(N_ / 64, 1, B_), 256>>>(Wq, bq, x, gq, CQK_);
    proj_kernel<32><<<dim3(N_ / 64, 1, B_), 256>>>(Wk, bk, x, gk, CQK_);
    proj_kernel<64><<<dim3(N_ / 64, C_ / 64, B_), 256>>>(Wv, bv, x, gv, C_);

    // bf16 hi/lo operand prep
    {
        size_t nqk = (size_t)B_ * CQK_ * N_;
        size_t nv  = (size_t)B_ * C_ * N_;
        convert_qk<<<(unsigned)((nqk + 255) / 256), 256>>>(gq, qh, ql);
        convert_qk<<<(unsigned)((nqk + 255) / 256), 256>>>(gk, kh, kl);
        convert_v<<<(unsigned)((nv + 255) / 256), 256>>>(gv, vh, vl);
    }

    // attention on tensor cores (mma.sync)
    flash_mma_kernel<<<dim3(N_ / 64, B_), 256, FL_SMEM>>>(qh, ql, kh, kl, vh, vl, go);

    // final projection
    proj_kernel<64><<<dim3(N_ / 64, C_ / 64, B_), 256>>>(Wf, bf, go, out, C_);
}

// round 6
// speedup vs baseline: 2.7941x; 1.4555x over previous
#include <cuda_runtime.h>
#include <cuda_bf16.h>
#include <cstdint>

static constexpr int B_   = 8;
static constexpr int C_   = 256;
static constexpr int CQK_ = 32;
static constexpr int N_   = 4096;

// Scratch
__device__ float g_o[(size_t)B_ * C_ * N_];
__device__ __align__(256) __nv_bfloat16 g_qh[(size_t)B_ * N_ * CQK_];
__device__ __align__(256) __nv_bfloat16 g_ql[(size_t)B_ * N_ * CQK_];
__device__ __align__(256) __nv_bfloat16 g_kh[(size_t)B_ * N_ * CQK_];
__device__ __align__(256) __nv_bfloat16 g_kl[(size_t)B_ * N_ * CQK_];
__device__ __align__(256) __nv_bfloat16 g_vh[(size_t)B_ * C_ * N_];

// ---------------- packed f32x2 ----------------
using u64_t = unsigned long long;
__device__ __forceinline__ u64_t pack2(float lo, float hi) {
    u64_t r; asm("mov.b64 %0, {%1, %2};" : "=l"(r) : "f"(lo), "f"(hi)); return r;
}
__device__ __forceinline__ u64_t bcast2(float x) { return pack2(x, x); }
__device__ __forceinline__ u64_t fma2(u64_t a, u64_t b, u64_t c) {
    u64_t d; asm("fma.rn.f32x2 %0, %1, %2, %3;" : "=l"(d) : "l"(a), "l"(b), "l"(c)); return d;
}
__device__ __forceinline__ float2 unpack2(u64_t a) {
    float2 f; asm("mov.b64 {%0, %1}, %2;" : "=f"(f.x), "=f"(f.y) : "l"(a)); return f;
}

// ---------------- mma / ldmatrix / cp.async ----------------
__device__ __forceinline__ uint32_t smem_u32(const void* p) {
    uint32_t a;
    asm("{ .reg .u64 t; cvta.to.shared.u64 t, %1; cvt.u32.u64 %0, t; }" : "=r"(a) : "l"(p));
    return a;
}
__device__ __forceinline__ void cpa16(uint32_t dst, const void* src) {
    asm volatile("cp.async.cg.shared.global [%0], [%1], 16;" :: "r"(dst), "l"(src) : "memory");
}
#define CPA_COMMIT() asm volatile("cp.async.commit_group;" ::: "memory")
#define CPA_WAIT(n)  asm volatile("cp.async.wait_group %0;" :: "n"(n) : "memory")

__device__ __forceinline__ void ldsm4(uint32_t addr, uint32_t* r) {
    asm volatile("ldmatrix.sync.aligned.m8n8.x4.shared.b16 {%0,%1,%2,%3}, [%4];"
                 : "=r"(r[0]), "=r"(r[1]), "=r"(r[2]), "=r"(r[3]) : "r"(addr));
}
__device__ __forceinline__ void mma16816(float* d, const uint32_t* a, uint32_t b0, uint32_t b1) {
    asm volatile("mma.sync.aligned.m16n8k16.row.col.f32.bf16.bf16.f32 "
                 "{%0,%1,%2,%3}, {%4,%5,%6,%7}, {%8,%9}, {%0,%1,%2,%3};"
                 : "+f"(d[0]), "+f"(d[1]), "+f"(d[2]), "+f"(d[3])
                 : "r"(a[0]), "r"(a[1]), "r"(a[2]), "r"(a[3]), "r"(b0), "r"(b1));
}
__device__ __forceinline__ uint32_t pack_bf16x2(float e0, float e1) {
    uint32_t r; asm("cvt.rn.bf16x2.f32 %0, %1, %2;" : "=r"(r) : "f"(e1), "f"(e0)); return r;
}
__device__ __forceinline__ float lo_bf16_f(uint32_t u) { return __uint_as_float(u << 16); }
__device__ __forceinline__ float hi_bf16_f(uint32_t u) { return __uint_as_float(u & 0xffff0000u); }
__device__ __forceinline__ void bf16_split(float v, __nv_bfloat16& h, __nv_bfloat16& l) {
    h = __float2bfloat16(v);
    l = __float2bfloat16(v - __bfloat162float(h));
}

// ---------------- Q/K projection: fp32 compute -> bf16 hi/lo [B][N][32] -------
__global__ __launch_bounds__(256)
void proj_qk_kernel(const float* __restrict__ W, const float* __restrict__ bias,
                    const float* __restrict__ X,
                    __nv_bfloat16* __restrict__ Yh, __nv_bfloat16* __restrict__ Yl)
{
    constexpr int BM = 32, BK = 32, BN = 64, TM = 2;
    __shared__ float Ws[BK][BM + 4];
    __shared__ float Xs[BK][BN];

    const int b  = blockIdx.z;
    const int n0 = blockIdx.x * BN;
    const float* Xb = X + (size_t)b * C_ * N_;

    const int tid = threadIdx.x;
    const int tm  = (tid / 16) * TM;
    const int tn  = (tid % 16) * 4;

    u64_t acc2[TM][2];
#pragma unroll
    for (int i = 0; i < TM; i++) { acc2[i][0] = pack2(0.f,0.f); acc2[i][1] = pack2(0.f,0.f); }

    for (int k0 = 0; k0 < C_; k0 += BK) {
        for (int i = tid; i < BM * BK; i += 256) {
            int m = i / BK, k = i % BK;
            Ws[k][m] = W[(size_t)m * C_ + (k0 + k)];
        }
        for (int i = tid; i < BK * BN / 4; i += 256) {
            int k = i / (BN / 4), n4 = (i % (BN / 4)) * 4;
            *(float4*)&Xs[k][n4] = *(const float4*)&Xb[(size_t)(k0 + k) * N_ + (n0 + n4)];
        }
        __syncthreads();
#pragma unroll
        for (int k = 0; k < BK; k++) {
            float2 w2 = *(const float2*)&Ws[k][tm];
            float4 x4 = *(const float4*)&Xs[k][tn];
            u64_t xp0 = pack2(x4.x, x4.y), xp1 = pack2(x4.z, x4.w);
            u64_t wb0 = bcast2(w2.x), wb1 = bcast2(w2.y);
            acc2[0][0] = fma2(xp0, wb0, acc2[0][0]);
            acc2[0][1] = fma2(xp1, wb0, acc2[0][1]);
            acc2[1][0] = fma2(xp0, wb1, acc2[1][0]);
            acc2[1][1] = fma2(xp1, wb1, acc2[1][1]);
        }
        __syncthreads();
    }
#pragma unroll
    for (int i = 0; i < TM; i++) {
        int m = tm + i;
        float bb = bias[m];
        float2 a0 = unpack2(acc2[i][0]), a1 = unpack2(acc2[i][1]);
        float vals[4] = {a0.x + bb, a0.y + bb, a1.x + bb, a1.y + bb};
#pragma unroll
        for (int j = 0; j < 4; j++) {
            size_t o = ((size_t)b * N_ + n0 + tn + j) * CQK_ + m;
            __nv_bfloat16 h, l; bf16_split(vals[j], h, l);
            Yh[o] = h; Yl[o] = l;
        }
    }
}

// ---------------- V projection: fp32 compute -> bf16 (hi only) [B][C][N] ------
__global__ __launch_bounds__(256)
void proj_vh_kernel(const float* __restrict__ W, const float* __restrict__ bias,
                    const float* __restrict__ X, __nv_bfloat16* __restrict__ Yh)
{
    constexpr int BM = 64, BK = 32, BN = 64, TM = 4;
    __shared__ float Ws[BK][BM + 4];
    __shared__ float Xs[BK][BN];

    const int b  = blockIdx.z;
    const int m0 = blockIdx.y * BM;
    const int n0 = blockIdx.x * BN;
    const float* Xb = X + (size_t)b * C_ * N_;

    const int tid = threadIdx.x;
    const int tm  = (tid / 16) * TM;
    const int tn  = (tid % 16) * 4;

    u64_t acc2[TM][2];
#pragma unroll
    for (int i = 0; i < TM; i++) { acc2[i][0] = pack2(0.f,0.f); acc2[i][1] = pack2(0.f,0.f); }

    for (int k0 = 0; k0 < C_; k0 += BK) {
        for (int i = tid; i < BM * BK; i += 256) {
            int m = i / BK, k = i % BK;
            Ws[k][m] = W[(size_t)(m0 + m) * C_ + (k0 + k)];
        }
        for (int i = tid; i < BK * BN / 4; i += 256) {
            int k = i / (BN / 4), n4 = (i % (BN / 4)) * 4;
            *(float4*)&Xs[k][n4] = *(const float4*)&Xb[(size_t)(k0 + k) * N_ + (n0 + n4)];
        }
        __syncthreads();
#pragma unroll
        for (int k = 0; k < BK; k++) {
            float4 w4 = *(const float4*)&Ws[k][tm];
            float wr[4] = {w4.x, w4.y, w4.z, w4.w};
            float4 x4 = *(const float4*)&Xs[k][tn];
            u64_t xp0 = pack2(x4.x, x4.y), xp1 = pack2(x4.z, x4.w);
#pragma unroll
            for (int i = 0; i < TM; i++) {
                u64_t wb = bcast2(wr[i]);
                acc2[i][0] = fma2(xp0, wb, acc2[i][0]);
                acc2[i][1] = fma2(xp1, wb, acc2[i][1]);
            }
        }
        __syncthreads();
    }
#pragma unroll
    for (int i = 0; i < TM; i++) {
        int m = m0 + tm + i;
        float bb = bias[m];
        float2 a0 = unpack2(acc2[i][0]), a1 = unpack2(acc2[i][1]);
        __nv_bfloat162 p01, p23;
        p01.x = __float2bfloat16(a0.x + bb); p01.y = __float2bfloat16(a0.y + bb);
        p23.x = __float2bfloat16(a1.x + bb); p23.y = __float2bfloat16(a1.y + bb);
        size_t base = ((size_t)b * C_ + m) * N_ + n0 + tn;
        *(__nv_bfloat162*)&Yh[base]     = p01;
        *(__nv_bfloat162*)&Yh[base + 2] = p23;
    }
}

// ---------------- final projection (fp32 in/out, known good) ----------------
__global__ __launch_bounds__(256)
void proj_f_kernel(const float* __restrict__ W, const float* __restrict__ bias,
                   const float* __restrict__ X, float* __restrict__ Y)
{
    constexpr int BM = 64, BK = 32, BN = 64, TM = 4;
    __shared__ float Ws[BK][BM + 4];
    __shared__ float Xs[BK][BN];

    const int b  = blockIdx.z;
    const int m0 = blockIdx.y * BM;
    const int n0 = blockIdx.x * BN;
    const float* Xb = X + (size_t)b * C_ * N_;
    float*       Yb = Y + (size_t)b * C_ * N_;

    const int tid = threadIdx.x;
    const int tm  = (tid / 16) * TM;
    const int tn  = (tid % 16) * 4;

    u64_t acc2[TM][2];
#pragma unroll
    for (int i = 0; i < TM; i++) { acc2[i][0] = pack2(0.f,0.f); acc2[i][1] = pack2(0.f,0.f); }

    for (int k0 = 0; k0 < C_; k0 += BK) {
        for (int i = tid; i < BM * BK; i += 256) {
            int m = i / BK, k = i % BK;
            Ws[k][m] = W[(size_t)(m0 + m) * C_ + (k0 + k)];
        }
        for (int i = tid; i < BK * BN / 4; i += 256) {
            int k = i / (BN / 4), n4 = (i % (BN / 4)) * 4;
            *(float4*)&Xs[k][n4] = *(const float4*)&Xb[(size_t)(k0 + k) * N_ + (n0 + n4)];
        }
        __syncthreads();
#pragma unroll
        for (int k = 0; k < BK; k++) {
            float4 w4 = *(const float4*)&Ws[k][tm];
            float wr[4] = {w4.x, w4.y, w4.z, w4.w};
            float4 x4 = *(const float4*)&Xs[k][tn];
            u64_t xp0 = pack2(x4.x, x4.y), xp1 = pack2(x4.z, x4.w);
#pragma unroll
            for (int i = 0; i < TM; i++) {
                u64_t wb = bcast2(wr[i]);
                acc2[i][0] = fma2(xp0, wb, acc2[i][0]);
                acc2[i][1] = fma2(xp1, wb, acc2[i][1]);
            }
        }
        __syncthreads();
    }
#pragma unroll
    for (int i = 0; i < TM; i++) {
        float bb = bias[m0 + tm + i];
        float2 a0 = unpack2(acc2[i][0]), a1 = unpack2(acc2[i][1]);
        float4 o4 = make_float4(a0.x + bb, a0.y + bb, a1.x + bb, a1.y + bb);
        *(float4*)&Yb[(size_t)(m0 + tm + i) * N_ + (n0 + tn)] = o4;
    }
}

// ---------------- flash attention on mma.sync ----------------
// 8 warps: warps 0-3 = producers (compute S/exp/P for rows (w&3)*16, share P via
// smem lane-mirror); warps 4-7 = consumers (same rows, other channel half).
// PV is 2-term (PhVh + PlVh): no Vl anywhere. QK is 3-term, computed once.
// smem layout (bytes):
//   [0,16384)      P exchange: hi 4x2048 @0, lo 4x2048 @8192  (overlaid: Q tile
//                  [0,10240) lives here only until qa fragments are loaded)
//   [16384,16640)  row sums (64 floats)
//   [16640,37120)  K bufs: 2 x (hi 5120 | lo 5120), rows 80 B
//   [37120,110848) V bufs: 2 x 36864 (hi only), rows 144 B
static constexpr int SP_HI = 0;
static constexpr int SP_LO = 8192;
static constexpr int S_INV = 16384;
static constexpr int SQH   = 0;
static constexpr int SQL   = 5120;
static constexpr int SKB   = 16640;
static constexpr int SVB   = 37120;
static constexpr int FL_SMEM = 110848;

__global__ __launch_bounds__(256, 2)
void flash_mma_kernel(const __nv_bfloat16* __restrict__ Qh, const __nv_bfloat16* __restrict__ Ql,
                      const __nv_bfloat16* __restrict__ Kh, const __nv_bfloat16* __restrict__ Kl,
                      const __nv_bfloat16* __restrict__ Vh, float* __restrict__ O)
{
    extern __shared__ char smem[];
    const uint32_t sb = smem_u32(smem);
    const int tid = threadIdx.x, lane = tid & 31, w = tid >> 5;
    const int qw = (w & 3) * 16;
    const int cbase = (w >> 2) * 128;
    const bool producer = (w < 4);
    const int b = blockIdx.y, q0 = blockIdx.x * 64;

    auto load_kv = [&](int kt, int bi) {
        const int j0 = kt * 64;
        for (int i = tid; i < 512; i += 256) {
            int half = i >> 8, r = (i >> 2) & 63, ch = i & 3;
            const __nv_bfloat16* src = (half ? Kl : Kh) + ((size_t)b * N_ + j0 + r) * CQK_ + ch * 8;
            cpa16(sb + SKB + bi * 10240 + half * 5120 + r * 80 + ch * 16, src);
        }
        for (int i = tid; i < 2048; i += 256) {
            int r = i >> 3, ch = i & 7;
            const __nv_bfloat16* src = Vh + ((size_t)b * C_ + r) * N_ + j0 + ch * 8;
            cpa16(sb + SVB + bi * 36864 + r * 144 + ch * 16, src);
        }
    };

    // prologue: Q + tiles 0,1
    for (int i = tid; i < 512; i += 256) {
        int half = i >> 8, r = (i >> 2) & 63, ch = i & 3;
        const __nv_bfloat16* src = (half ? Ql : Qh) + ((size_t)b * N_ + q0 + r) * CQK_ + ch * 8;
        cpa16(sb + (half ? SQL : SQH) + r * 80 + ch * 16, src);
    }
    load_kv(0, 0); CPA_COMMIT();
    load_kv(1, 1); CPA_COMMIT();
    CPA_WAIT(1);
    __syncthreads();

    // Q A-fragments (producers only)
    uint32_t qa[2][2][4];
    if (producer) {
#pragma unroll
        for (int hl = 0; hl < 2; hl++)
#pragma unroll
            for (int kc = 0; kc < 2; kc++) {
                uint32_t addr = sb + (hl ? SQL : SQH)
                              + (uint32_t)(qw + (lane & 15)) * 80
                              + (uint32_t)(kc * 16 + (lane >> 4) * 8) * 2;
                ldsm4(addr, qa[hl][kc]);
            }
    }
    __syncthreads();   // Q region is dead; P exchange may now overwrite it

    float oacc[16][4];
#pragma unroll
    for (int i = 0; i < 16; i++)
#pragma unroll
        for (int j = 0; j < 4; j++) oacc[i][j] = 0.f;
    float rsum0 = 0.f, rsum1 = 0.f;

    for (int kt = 0; kt < 64; kt++) {
        const int bi = kt & 1;
        const uint32_t vh_b = sb + SVB + bi * 36864;

        uint32_t pah[4][4], pal[4][4];

        if (producer) {
            const uint32_t kh_b = sb + SKB + bi * 10240, kl_b = kh_b + 5120;
            // --- S = QK^T (3-term bf16 split) ---
            float sacc[8][4];
#pragma unroll
            for (int i = 0; i < 8; i++)
#pragma unroll
                for (int j = 0; j < 4; j++) sacc[i][j] = 0.f;
#pragma unroll
            for (int kc = 0; kc < 2; kc++)
#pragma unroll
                for (int nbp = 0; nbp < 4; nbp++) {
                    uint32_t off = (uint32_t)((nbp * 2 + ((lane >> 4) & 1)) * 8 + (lane & 7)) * 80
                                 + (uint32_t)(kc * 16 + ((lane >> 3) & 1) * 8) * 2;
                    uint32_t bh[4], bl[4];
                    ldsm4(kh_b + off, bh);
                    ldsm4(kl_b + off, bl);
                    mma16816(sacc[2*nbp],   qa[0][kc], bh[0], bh[1]);
                    mma16816(sacc[2*nbp+1], qa[0][kc], bh[2], bh[3]);
                    mma16816(sacc[2*nbp],   qa[1][kc], bh[0], bh[1]);
                    mma16816(sacc[2*nbp+1], qa[1][kc], bh[2], bh[3]);
                    mma16816(sacc[2*nbp],   qa[0][kc], bl[0], bl[1]);
                    mma16816(sacc[2*nbp+1], qa[0][kc], bl[2], bl[3]);
                }
            // --- P = exp(S); pack bf16 hi/lo ---
#pragma unroll
            for (int nb = 0; nb < 8; nb++) {
                float e0 = __expf(sacc[nb][0]);
                float e1 = __expf(sacc[nb][1]);
                float e2 = __expf(sacc[nb][2]);
                float e3 = __expf(sacc[nb][3]);
                rsum0 += e0 + e1;
                rsum1 += e2 + e3;
                int kj = nb >> 1, o = (nb & 1) * 2;
                uint32_t h01 = pack_bf16x2(e0, e1);
                uint32_t h23 = pack_bf16x2(e2, e3);
                pah[kj][o]     = h01;
                pah[kj][o + 1] = h23;
                pal[kj][o]     = pack_bf16x2(e0 - lo_bf16_f(h01), e1 - hi_bf16_f(h01));
                pal[kj][o + 1] = pack_bf16x2(e2 - lo_bf16_f(h23), e3 - hi_bf16_f(h23));
            }
            // --- mirror P fragments to smem for partner warp (lane-for-lane) ---
            char* ph_dst = smem + SP_HI + (w & 3) * 2048 + lane * 16;
            char* pl_dst = smem + SP_LO + (w & 3) * 2048 + lane * 16;
#pragma unroll
            for (int kj = 0; kj < 4; kj++) {
                *(uint4*)(ph_dst + kj * 512) = make_uint4(pah[kj][0], pah[kj][1], pah[kj][2], pah[kj][3]);
                *(uint4*)(pl_dst + kj * 512) = make_uint4(pal[kj][0], pal[kj][1], pal[kj][2], pal[kj][3]);
            }
        }
        __syncthreads();   // P visible to consumers

        if (!producer) {
            const char* ph_src = smem + SP_HI + (w & 3) * 2048 + lane * 16;
            const char* pl_src = smem + SP_LO + (w & 3) * 2048 + lane * 16;
#pragma unroll
            for (int kj = 0; kj < 4; kj++) {
                uint4 h4 = *(const uint4*)(ph_src + kj * 512);
                uint4 l4 = *(const uint4*)(pl_src + kj * 512);
                pah[kj][0] = h4.x; pah[kj][1] = h4.y; pah[kj][2] = h4.z; pah[kj][3] = h4.w;
                pal[kj][0] = l4.x; pal[kj][1] = l4.y; pal[kj][2] = l4.z; pal[kj][3] = l4.w;
            }
        }

        // --- O += P V^T (2-term: PhVh + PlVh) over this warp's 128 channels ---
#pragma unroll
        for (int cb = 0; cb < 16; cb++) {
            uint32_t rowoff = (uint32_t)(cbase + cb * 8 + (lane & 7)) * 144;
            uint32_t vfh[8];
#pragma unroll
            for (int kjp = 0; kjp < 2; kjp++) {
                uint32_t off = rowoff + (uint32_t)(kjp * 32 + (lane >> 3) * 8) * 2;
                ldsm4(vh_b + off, &vfh[4 * kjp]);
            }
#pragma unroll
            for (int kj = 0; kj < 4; kj++) {
                int ix = (kj >> 1) * 4 + (kj & 1) * 2;
                mma16816(oacc[cb], pah[kj], vfh[ix], vfh[ix + 1]);
                mma16816(oacc[cb], pal[kj], vfh[ix], vfh[ix + 1]);
            }
        }

        // --- pipeline: refill this buffer with tile kt+2 ---
        __syncthreads();
        if (kt + 2 < 64) load_kv(kt + 2, bi);
        CPA_COMMIT();
        CPA_WAIT(1);
        __syncthreads();
    }

    // row sums -> smem (producers own them)
    float* sinv = (float*)(smem + S_INV);
    if (producer) {
        rsum0 += __shfl_xor_sync(0xffffffffu, rsum0, 1);
        rsum0 += __shfl_xor_sync(0xffffffffu, rsum0, 2);
        rsum1 += __shfl_xor_sync(0xffffffffu, rsum1, 1);
        rsum1 += __shfl_xor_sync(0xffffffffu, rsum1, 2);
        if ((lane & 3) == 0) {
            sinv[qw + (lane >> 2)]     = rsum0;
            sinv[qw + 8 + (lane >> 2)] = rsum1;
        }
    }
    __syncthreads();
    const float inv0 = 1.f / sinv[qw + (lane >> 2)];
    const float inv1 = 1.f / sinv[qw + 8 + (lane >> 2)];

    const int qg = q0 + qw + (lane >> 2);
    float* Ob = O + (size_t)b * C_ * N_;
#pragma unroll
    for (int cb = 0; cb < 16; cb++) {
        int c = cbase + cb * 8 + (lane & 3) * 2;
        Ob[(size_t)c * N_ + qg]           = oacc[cb][0] * inv0;
        Ob[(size_t)(c + 1) * N_ + qg]     = oacc[cb][1] * inv0;
        Ob[(size_t)c * N_ + qg + 8]       = oacc[cb][2] * inv1;
        Ob[(size_t)(c + 1) * N_ + qg + 8] = oacc[cb][3] * inv1;
    }
}

// ---------------- kernel_launch ----------------
extern "C" void kernel_launch(void* const* d_in, const int* in_sizes, int n_in,
                              void* d_out, int out_size)
{
    (void)in_sizes; (void)n_in; (void)out_size;
    const float* x  = (const float*)d_in[0];
    const float* Wq = (const float*)d_in[1];
    const float* bq = (const float*)d_in[2];
    const float* Wk = (const float*)d_in[3];
    const float* bk = (const float*)d_in[4];
    const float* Wv = (const float*)d_in[5];
    const float* bv = (const float*)d_in[6];
    const float* Wf = (const float*)d_in[7];
    const float* bf = (const float*)d_in[8];
    float* out = (float*)d_out;

    float* go;
    __nv_bfloat16 *qh, *ql, *kh, *kl, *vh;
    cudaGetSymbolAddress((void**)&go, g_o);
    cudaGetSymbolAddress((void**)&qh, g_qh);
    cudaGetSymbolAddress((void**)&ql, g_ql);
    cudaGetSymbolAddress((void**)&kh, g_kh);
    cudaGetSymbolAddress((void**)&kl, g_kl);
    cudaGetSymbolAddress((void**)&vh, g_vh);

    cudaFuncSetAttribute(flash_mma_kernel,
                         cudaFuncAttributeMaxDynamicSharedMemorySize, FL_SMEM);

    // projections with fused bf16 hi/lo emission
    proj_qk_kernel<<<dim3(N_ / 64, 1, B_), 256>>>(Wq, bq, x, qh, ql);
    proj_qk_kernel<<<dim3(N_ / 64, 1, B_), 256>>>(Wk, bk, x, kh, kl);
    proj_vh_kernel<<<dim3(N_ / 64, C_ / 64, B_), 256>>>(Wv, bv, x, vh);

    // attention on tensor cores
    flash_mma_kernel<<<dim3(N_ / 64, B_), 256, FL_SMEM>>>(qh, ql, kh, kl, vh, go);

    // final projection
    proj_f_kernel<<<dim3(N_ / 64, C_ / 64, B_), 256>>>(Wf, bf, go, out);
}